// round 1
// baseline (speedup 1.0000x reference)
#include <cuda_runtime.h>
#include <math.h>

// Problem constants
#define B   32
#define QL  16
#define KL  8192
#define D   512
#define INV_SQRT_D 0.044194173824159216f   // 1/sqrt(512)

#define KSPLIT1 32
#define KCHUNK1 (KL / KSPLIT1)   // 256
#define KSPLIT3 32
#define KCHUNK3 (KL / KSPLIT3)   // 256

// Scratch (allocations are forbidden; use device globals)
__device__ float g_score[B * KL];                 // 1 MB: scores, then weights (in-place)
__device__ float g_partial[B * KSPLIT3 * D];      // 2 MB: split-K partials

// ---------------------------------------------------------------------------
// Kernel 1: s[b,k] = (q0[b] . key[b,k]) / sqrt(D) * trust[b,k]
// One warp per key row; q staged in smem; float4 loads (fully coalesced).
// grid (KSPLIT1, B), block 256 (8 warps)
// ---------------------------------------------------------------------------
__global__ void score_kernel(const float* __restrict__ q,
                             const float* __restrict__ key,
                             const float* __restrict__ trust)
{
    const int b  = blockIdx.y;
    const int k0 = blockIdx.x * KCHUNK1;

    __shared__ float qs[D];
    const float* qb = q + (size_t)b * QL * D;     // q0 = query[b, 0, :]
    for (int i = threadIdx.x; i < D; i += blockDim.x) qs[i] = qb[i];
    __syncthreads();

    const int warp = threadIdx.x >> 5;
    const int lane = threadIdx.x & 31;
    const float4* qs4 = (const float4*)qs;

    for (int kk = warp; kk < KCHUNK1; kk += 8) {
        const int k = k0 + kk;
        const float4* kv4 = (const float4*)(key + ((size_t)b * KL + k) * D);
        float acc = 0.0f;
        #pragma unroll
        for (int i = 0; i < 4; i++) {
            float4 kv = kv4[lane + i * 32];
            float4 qv = qs4[lane + i * 32];
            acc += kv.x * qv.x + kv.y * qv.y + kv.z * qv.z + kv.w * qv.w;
        }
        #pragma unroll
        for (int o = 16; o > 0; o >>= 1)
            acc += __shfl_xor_sync(0xffffffffu, acc, o);
        if (lane == 0)
            g_score[b * KL + k] = acc * INV_SQRT_D * trust[b * KL + k];
    }
}

// ---------------------------------------------------------------------------
// Kernel 2: per-batch stable softmax with trust re-weighting (denominators
// of the inner softmax cancel):  w[k] = exp(s[k]-m)*t[k] / sum_j exp(s[j]-m)*t[j]
// grid (B), block 256. In-place on g_score.
// ---------------------------------------------------------------------------
__global__ void softmax_kernel(const float* __restrict__ trust)
{
    const int b = blockIdx.x;
    float* s = g_score + b * KL;
    const float* t = trust + b * KL;

    const int tid  = threadIdx.x;
    const int warp = tid >> 5;
    const int lane = tid & 31;
    __shared__ float red[8];
    __shared__ float m_s, invz_s;

    // --- pass 1: max ---
    float m = -INFINITY;
    for (int k = tid; k < KL; k += 256) m = fmaxf(m, s[k]);
    #pragma unroll
    for (int o = 16; o > 0; o >>= 1) m = fmaxf(m, __shfl_xor_sync(0xffffffffu, m, o));
    if (lane == 0) red[warp] = m;
    __syncthreads();
    if (warp == 0) {
        float v = (lane < 8) ? red[lane] : -INFINITY;
        #pragma unroll
        for (int o = 4; o > 0; o >>= 1) v = fmaxf(v, __shfl_xor_sync(0xffffffffu, v, o));
        if (lane == 0) m_s = v;
    }
    __syncthreads();
    m = m_s;

    // --- pass 2: e = exp(s-m)*t, store, accumulate sum ---
    float z = 0.0f;
    for (int k = tid; k < KL; k += 256) {
        float e = __expf(s[k] - m) * t[k];
        s[k] = e;
        z += e;
    }
    #pragma unroll
    for (int o = 16; o > 0; o >>= 1) z += __shfl_xor_sync(0xffffffffu, z, o);
    if (lane == 0) red[warp] = z;
    __syncthreads();
    if (warp == 0) {
        float v = (lane < 8) ? red[lane] : 0.0f;
        #pragma unroll
        for (int o = 4; o > 0; o >>= 1) v += __shfl_xor_sync(0xffffffffu, v, o);
        if (lane == 0) invz_s = 1.0f / v;
    }
    __syncthreads();
    const float invz = invz_s;

    // --- pass 3: normalize ---
    for (int k = tid; k < KL; k += 256) s[k] *= invz;
}

// ---------------------------------------------------------------------------
// Kernel 3: split-K weighted value sum.
// Each block: (ksplit, b). 128 threads, each owns 4 contiguous d (float4).
// partial[b, split, d] = sum_{k in chunk} w[k] * value[b,k,d]
// Deterministic (no atomics).
// ---------------------------------------------------------------------------
__global__ void av_kernel(const float* __restrict__ value)
{
    const int b  = blockIdx.y;
    const int k0 = blockIdx.x * KCHUNK3;

    __shared__ float ws[KCHUNK3];
    for (int i = threadIdx.x; i < KCHUNK3; i += 128)
        ws[i] = g_score[b * KL + k0 + i];
    __syncthreads();

    const float4* vb = (const float4*)(value + ((size_t)b * KL + k0) * D) + threadIdx.x;

    float4 acc = make_float4(0.0f, 0.0f, 0.0f, 0.0f);
    #pragma unroll 8
    for (int kk = 0; kk < KCHUNK3; kk++) {
        float4 v = vb[(size_t)kk * (D / 4)];
        float  w = ws[kk];
        acc.x += w * v.x;
        acc.y += w * v.y;
        acc.z += w * v.z;
        acc.w += w * v.w;
    }

    float4* out4 = (float4*)(g_partial + ((size_t)(b * KSPLIT3 + blockIdx.x)) * D);
    out4[threadIdx.x] = acc;
}

// ---------------------------------------------------------------------------
// Kernel 4: reduce split-K partials into d_out.
// grid (B*D/256), block 256; one output element per thread.
// ---------------------------------------------------------------------------
__global__ void reduce_kernel(float* __restrict__ out)
{
    const int idx = blockIdx.x * 256 + threadIdx.x;   // idx = b*D + d
    const int b = idx / D;
    const int d = idx - b * D;
    float acc = 0.0f;
    #pragma unroll
    for (int s = 0; s < KSPLIT3; s++)
        acc += g_partial[(size_t)(b * KSPLIT3 + s) * D + d];
    out[idx] = acc;
}

// ---------------------------------------------------------------------------
extern "C" void kernel_launch(void* const* d_in, const int* in_sizes, int n_in,
                              void* d_out, int out_size)
{
    const float* query = (const float*)d_in[0];   // (B, QL, D)
    const float* key   = (const float*)d_in[1];   // (B, KL, D)
    const float* value = (const float*)d_in[2];   // (B, KL, D)
    const float* trust = (const float*)d_in[3];   // (B, 1, KL)
    float* out = (float*)d_out;                   // (B, 1, D)

    (void)in_sizes; (void)n_in; (void)out_size;

    dim3 g1(KSPLIT1, B);
    score_kernel<<<g1, 256>>>(query, key, trust);

    softmax_kernel<<<B, 256>>>(trust);

    dim3 g3(KSPLIT3, B);
    av_kernel<<<g3, 128>>>(value);

    reduce_kernel<<<(B * D) / 256, 256>>>(out);
}